// round 6
// baseline (speedup 1.0000x reference)
#include <cuda_runtime.h>
#include <stdint.h>

#define NN 50000
#define DD 128
#define RR 16
#define EE 1600000

// ---------------- device scratch (no allocs allowed) ----------------
__device__ __align__(16) float g_msg[(size_t)RR * NN * DD];  // scaled segment means
__device__ __align__(16) float g_h1[(size_t)NN * DD];        // layer-1 output
__device__ int   g_cnt_rel[RR * NN];
__device__ __align__(16) float g_inv[RR * NN];
__device__ int   g_cnt_node[NN];
__device__ int   g_off[NN + 1];
__device__ int   g_cursor[NN];
__device__ unsigned long long g_rec[EE];   // packed (dst | src<<20 | rel<<40)
__device__ unsigned int g_csr[EE];         // dst-sorted: (src | rel<<20)
__device__ int   g_is64;                   // 1 if edge arrays are int64, else int32

// ---------------- helpers ----------------
__device__ __forceinline__ float tf32r(float x) {
    uint32_t u;
    asm("cvt.rna.tf32.f32 %0, %1;" : "=r"(u) : "f"(x));
    return __uint_as_float(u);
}

__device__ __forceinline__ void mma8(float* c, const uint32_t* a, const uint32_t* b) {
    asm volatile(
        "mma.sync.aligned.m16n8k8.row.col.f32.tf32.tf32.f32 "
        "{%0,%1,%2,%3}, {%4,%5,%6,%7}, {%8,%9}, {%0,%1,%2,%3};"
        : "+f"(c[0]), "+f"(c[1]), "+f"(c[2]), "+f"(c[3])
        : "r"(a[0]), "r"(a[1]), "r"(a[2]), "r"(a[3]), "r"(b[0]), "r"(b[1]));
}

// ---------------- dtype detector ----------------
// If edge_type is int64 with values in [0,16), every odd 32-bit word of its
// storage is zero. For int32 data the odds of 2048 sampled odd words all being
// zero are (1/16)^2048 ~ 0. One block; deterministic.
__global__ void detect_kernel(const unsigned int* __restrict__ et_words) {
    __shared__ int any_nonzero;
    if (threadIdx.x == 0) any_nonzero = 0;
    __syncthreads();
    // sample first 2048 odd words (within first 4096 words = 2048 edges min either way)
    for (int i = threadIdx.x; i < 2048; i += blockDim.x) {
        if (et_words[2 * i + 1] != 0u) any_nonzero = 1;
    }
    __syncthreads();
    if (threadIdx.x == 0) g_is64 = any_nonzero ? 0 : 1;
}

// ---------------- setup kernels (structure shared by both layers) ----------------
__global__ void zero_cnt_kernel() {
    int i = blockIdx.x * blockDim.x + threadIdx.x;
    const int tot = RR * NN + NN;
    for (; i < tot; i += gridDim.x * blockDim.x) {
        if (i < RR * NN) g_cnt_rel[i] = 0;
        else             g_cnt_node[i - RR * NN] = 0;
    }
}

__global__ void count_kernel(const void* __restrict__ ei_raw,
                             const void* __restrict__ et_raw) {
    const int is64 = g_is64;
    int e = blockIdx.x * blockDim.x + threadIdx.x;
    for (; e < EE; e += gridDim.x * blockDim.x) {
        int s, d, r;
        if (is64) {
            const long long* ei = (const long long*)ei_raw;
            const long long* et = (const long long*)et_raw;
            s = (int)ei[e];
            d = (int)ei[(size_t)EE + e];
            r = (int)et[e];
        } else {
            const int* ei = (const int*)ei_raw;
            const int* et = (const int*)et_raw;
            s = ei[e];
            d = ei[EE + e];
            r = et[e];
        }
        // defensive: a bad edge can only be dropped, never trap
        if ((unsigned)s >= NN || (unsigned)d >= NN || (unsigned)r >= RR) {
            g_rec[e] = ~0ull;
            continue;
        }
        g_rec[e] = (unsigned long long)d
                 | ((unsigned long long)s << 20)
                 | ((unsigned long long)r << 40);
        atomicAdd(&g_cnt_rel[r * NN + d], 1);
        atomicAdd(&g_cnt_node[d], 1);
    }
}

__global__ void inv_kernel() {
    int i = blockIdx.x * blockDim.x + threadIdx.x;
    for (; i < RR * NN; i += gridDim.x * blockDim.x) {
        int c = g_cnt_rel[i];
        g_inv[i] = 1.0f / (float)(c > 1 ? c : 1);
    }
}

// single-block exclusive scan over node counts (NN = 50000)
__global__ void scan_kernel() {
    __shared__ int part[1024];
    const int tid = threadIdx.x;
    const int CH = (NN + 1023) / 1024;  // 49
    int base = tid * CH;
    int s = 0;
    for (int j = 0; j < CH; j++) {
        int idx = base + j;
        if (idx < NN) s += g_cnt_node[idx];
    }
    part[tid] = s;
    __syncthreads();
    for (int ofs = 1; ofs < 1024; ofs <<= 1) {
        int add = (tid >= ofs) ? part[tid - ofs] : 0;
        __syncthreads();
        part[tid] += add;
        __syncthreads();
    }
    int excl = (tid > 0) ? part[tid - 1] : 0;
    int run = excl;
    for (int j = 0; j < CH; j++) {
        int idx = base + j;
        if (idx < NN) {
            g_off[idx] = run;
            g_cursor[idx] = run;
            run += g_cnt_node[idx];
        }
    }
    if (tid == 1023) g_off[NN] = part[1023];
}

__global__ void csr_kernel() {
    int e = blockIdx.x * blockDim.x + threadIdx.x;
    for (; e < EE; e += gridDim.x * blockDim.x) {
        unsigned long long rc = g_rec[e];
        if (rc == ~0ull) continue;  // dropped edge
        int d = (int)(rc & 0xFFFFFu);
        int s = (int)((rc >> 20) & 0xFFFFFu);
        int r = (int)(rc >> 40);
        int pos = atomicAdd(&g_cursor[d], 1);
        g_csr[pos] = (unsigned)s | ((unsigned)r << 20);
    }
}

// ---------------- per-layer aggregation: one block per dst node ----------------
// use_h1 != 0 -> read node features from g_h1 instead of the external pointer.
__global__ void agg_kernel(const float* __restrict__ Xext, int use_h1) {
    __shared__ float acc[RR][DD];
    const float* __restrict__ X = use_h1 ? (const float*)g_h1 : Xext;
    const int i = blockIdx.x;
    const int t = threadIdx.x;
#pragma unroll
    for (int r = 0; r < RR; r++) acc[r][t] = 0.0f;
    const int beg = g_off[i];
    const int end = g_off[i + 1];
    for (int p = beg; p < end; p++) {
        unsigned c = __ldg(&g_csr[p]);
        int s = (int)(c & 0xFFFFFu);
        int r = (int)(c >> 20);
        acc[r][t] += __ldg(&X[(size_t)s * DD + t]);
    }
#pragma unroll
    for (int r = 0; r < RR; r++) {
        float iv = g_inv[r * NN + i];
        g_msg[((size_t)r * NN + i) * DD + t] = acc[r][t] * iv;
    }
}

// ---------------- fused GEMM: Y = relu([msg_scaled | X] @ [W ; root] + bias) ---
// M = 50000 (128-row tiles), N = 128, K = R*D + D = 2176 (32-col chunks)
// Static shared only (<48KB): As 128x36, Bs 32x132  ->  35,328 bytes.
#define ASTR 36
#define BSTR 132

__global__ void __launch_bounds__(256, 2)
gemm_kernel(const float* __restrict__ Xext,
            const float* __restrict__ W,
            const float* __restrict__ root,
            const float* __restrict__ bias,
            float* __restrict__ Yext,
            int io_mode)  // bit0: input from g_h1; bit1: output to g_h1
{
    __shared__ __align__(16) float As[128 * ASTR];
    __shared__ __align__(16) float Bs[32 * BSTR];

    const float* __restrict__ Xin = (io_mode & 1) ? (const float*)g_h1 : Xext;
    float* __restrict__ Y = (io_mode & 2) ? (float*)g_h1 : Yext;

    const int tid = threadIdx.x;
    const int row0 = blockIdx.x * 128;
    const int warp = tid >> 5;
    const int lane = tid & 31;
    const int wm = warp & 3;   // 4 warps over M (32 rows each)
    const int wn = warp >> 2;  // 2 warps over N (64 cols each)

    float acc[2][8][4];
#pragma unroll
    for (int mi = 0; mi < 2; mi++)
#pragma unroll
        for (int ni = 0; ni < 8; ni++)
#pragma unroll
            for (int q = 0; q < 4; q++) acc[mi][ni][q] = 0.0f;

    for (int c = 0; c < 68; c++) {
        const float* Ab;
        const float* Bb;
        if (c < 64) {
            int r = c >> 2;
            int koff = (c & 3) * 32;
            Ab = g_msg + ((size_t)r * NN + row0) * DD + koff;
            Bb = W + (size_t)r * DD * DD + (size_t)koff * DD;
        } else {
            int d0 = (c - 64) * 32;
            Ab = Xin + (size_t)row0 * DD + d0;
            Bb = root + (size_t)d0 * DD;
        }
        __syncthreads();
        // A tile: 128 x 32 (4 float4 per thread)
#pragma unroll
        for (int it = 0; it < 4; it++) {
            int j = tid + 256 * it;
            int rA = j >> 3;
            int cg = j & 7;
            float4 v;
            if (row0 + rA < NN) v = *(const float4*)(Ab + (size_t)rA * DD + cg * 4);
            else                v = make_float4(0.f, 0.f, 0.f, 0.f);
            v.x = tf32r(v.x); v.y = tf32r(v.y); v.z = tf32r(v.z); v.w = tf32r(v.w);
            *(float4*)(As + rA * ASTR + cg * 4) = v;
        }
        // B tile: 32 x 128 (4 float4 per thread)
#pragma unroll
        for (int it = 0; it < 4; it++) {
            int j = tid + 256 * it;
            int rB = j >> 5;
            int cg = j & 31;
            float4 v = *(const float4*)(Bb + (size_t)rB * DD + cg * 4);
            v.x = tf32r(v.x); v.y = tf32r(v.y); v.z = tf32r(v.z); v.w = tf32r(v.w);
            *(float4*)(Bs + rB * BSTR + cg * 4) = v;
        }
        __syncthreads();

        const uint32_t* Au = (const uint32_t*)As;
        const uint32_t* Bu = (const uint32_t*)Bs;
#pragma unroll
        for (int ks = 0; ks < 4; ks++) {
            int k8 = ks * 8;
            uint32_t a[2][4];
#pragma unroll
            for (int mi = 0; mi < 2; mi++) {
                int rb = wm * 32 + mi * 16 + (lane >> 2);
                int cb = k8 + (lane & 3);
                a[mi][0] = Au[rb * ASTR + cb];
                a[mi][1] = Au[(rb + 8) * ASTR + cb];
                a[mi][2] = Au[rb * ASTR + cb + 4];
                a[mi][3] = Au[(rb + 8) * ASTR + cb + 4];
            }
            uint32_t b[8][2];
#pragma unroll
            for (int ni = 0; ni < 8; ni++) {
                int col = wn * 64 + ni * 8 + (lane >> 2);
                int kb = k8 + (lane & 3);
                b[ni][0] = Bu[kb * BSTR + col];
                b[ni][1] = Bu[(kb + 4) * BSTR + col];
            }
#pragma unroll
            for (int mi = 0; mi < 2; mi++)
#pragma unroll
                for (int ni = 0; ni < 8; ni++)
                    mma8(acc[mi][ni], a[mi], b[ni]);
        }
    }

    // epilogue: + bias, relu, store
#pragma unroll
    for (int mi = 0; mi < 2; mi++) {
        int r0 = row0 + wm * 32 + mi * 16 + (lane >> 2);
#pragma unroll
        for (int ni = 0; ni < 8; ni++) {
            int cc = wn * 64 + ni * 8 + (lane & 3) * 2;
            float bi0 = __ldg(&bias[cc]);
            float bi1 = __ldg(&bias[cc + 1]);
            if (r0 < NN) {
                float y0 = fmaxf(acc[mi][ni][0] + bi0, 0.0f);
                float y1 = fmaxf(acc[mi][ni][1] + bi1, 0.0f);
                *(float2*)(Y + (size_t)r0 * DD + cc) = make_float2(y0, y1);
            }
            if (r0 + 8 < NN) {
                float y2 = fmaxf(acc[mi][ni][2] + bi0, 0.0f);
                float y3 = fmaxf(acc[mi][ni][3] + bi1, 0.0f);
                *(float2*)(Y + (size_t)(r0 + 8) * DD + cc) = make_float2(y2, y3);
            }
        }
    }
}

// ---------------- launch (kernel launches ONLY — no other CUDA APIs) ----------
extern "C" void kernel_launch(void* const* d_in, const int* in_sizes, int n_in,
                              void* d_out, int out_size) {
    const float* x     = (const float*)d_in[0];
    const void*  ei    = d_in[1];   // int32 or int64, detected on device
    const void*  et    = d_in[2];
    const float* W1    = (const float*)d_in[3];
    const float* root1 = (const float*)d_in[4];
    const float* b1    = (const float*)d_in[5];
    const float* W2    = (const float*)d_in[6];
    const float* root2 = (const float*)d_in[7];
    const float* b2    = (const float*)d_in[8];
    float* out         = (float*)d_out;

    // structure (shared by both layers)
    detect_kernel<<<1, 256>>>((const unsigned int*)et);
    zero_cnt_kernel<<<1024, 256>>>();
    count_kernel<<<2048, 256>>>(ei, et);
    inv_kernel<<<1024, 256>>>();
    scan_kernel<<<1, 1024>>>();
    csr_kernel<<<2048, 256>>>();

    const int gemm_blocks = (NN + 127) / 128;

    // layer 1: read x, write h1 (internal)
    agg_kernel<<<NN, 128>>>(x, 0);
    gemm_kernel<<<gemm_blocks, 256>>>(x, W1, root1, b1, out, /*io_mode=*/2);

    // layer 2: read h1 (internal), write d_out
    agg_kernel<<<NN, 128>>>(nullptr, 1);
    gemm_kernel<<<gemm_blocks, 256>>>(nullptr, W2, root2, b2, out, /*io_mode=*/1);
}